// round 1
// baseline (speedup 1.0000x reference)
#include <cuda_runtime.h>
#include <cstdint>

#define Bn 32
#define An 8400
#define NCn 80
#define Kn 1024
#define Gn 32
#define NSUPn 16
#define MAXDET 300

// -------- scratch (no allocs allowed) --------
__device__ unsigned long long g_keys[Bn * An];   // (conf_bits<<32) | (0xFFFFFFFF - a)
__device__ float4             g_boxes[Bn * An];  // x1 y1 x2 y2

// ============================================================
// Kernel 1: decode boxes + conf=max(scores) (no argmax here)
// Split max across fma pipe (float FMNMX) and alu pipe (uint IMNMX
// on bit patterns -- valid since scores >= 0).
// ============================================================
__global__ void k1_scores(const float* __restrict__ preds) {
    const int APQ = An / 4;
    int t = blockIdx.x * blockDim.x + threadIdx.x;
    if (t >= Bn * APQ) return;
    int b  = t / APQ;
    int a4 = (t - b * APQ) * 4;
    const float* base = preds + (size_t)b * (4 + NCn) * An;

    float4 cx = *(const float4*)(base + (size_t)0 * An + a4);
    float4 cy = *(const float4*)(base + (size_t)1 * An + a4);
    float4 w  = *(const float4*)(base + (size_t)2 * An + a4);
    float4 h  = *(const float4*)(base + (size_t)3 * An + a4);

    float4 mf = make_float4(0.f, 0.f, 0.f, 0.f);
    uint4  mi = make_uint4(0u, 0u, 0u, 0u);

#pragma unroll 8
    for (int c = 4; c < 44; ++c) {
        float4 s = *(const float4*)(base + (size_t)c * An + a4);
        mf.x = fmaxf(mf.x, s.x); mf.y = fmaxf(mf.y, s.y);
        mf.z = fmaxf(mf.z, s.z); mf.w = fmaxf(mf.w, s.w);
    }
#pragma unroll 8
    for (int c = 44; c < 84; ++c) {
        float4 s = *(const float4*)(base + (size_t)c * An + a4);
        mi.x = max(mi.x, __float_as_uint(s.x));
        mi.y = max(mi.y, __float_as_uint(s.y));
        mi.z = max(mi.z, __float_as_uint(s.z));
        mi.w = max(mi.w, __float_as_uint(s.w));
    }

    float conf[4];
    conf[0] = fmaxf(mf.x, __uint_as_float(mi.x));
    conf[1] = fmaxf(mf.y, __uint_as_float(mi.y));
    conf[2] = fmaxf(mf.z, __uint_as_float(mi.z));
    conf[3] = fmaxf(mf.w, __uint_as_float(mi.w));
    float cxa[4] = {cx.x, cx.y, cx.z, cx.w};
    float cya[4] = {cy.x, cy.y, cy.z, cy.w};
    float wa[4]  = {w.x,  w.y,  w.z,  w.w};
    float ha[4]  = {h.x,  h.y,  h.z,  h.w};

#pragma unroll
    for (int k = 0; k < 4; ++k) {
        int a = a4 + k;
        float tc = (conf[k] > 0.25f) ? conf[k] : 0.0f;
        unsigned long long key =
            ((unsigned long long)__float_as_uint(tc) << 32) |
            (unsigned long long)(0xFFFFFFFFu - (unsigned)a);
        g_keys[(size_t)b * An + a] = key;
        // exact per-op rounding (no FMA contraction), matches reference
        float hw = __fmul_rn(wa[k], 0.5f);
        float hh = __fmul_rn(ha[k], 0.5f);
        float x1 = __fsub_rn(cxa[k], hw);
        float y1 = __fsub_rn(cya[k], hh);
        float x2 = __fadd_rn(cxa[k], hw);
        float y2 = __fadd_rn(cya[k], hh);
        g_boxes[(size_t)b * An + a] = make_float4(x1, y1, x2, y2);
    }
}

// exact-rounded IoU matching the reference formula:
// inter / ((areaA + areaB) - inter + 1e-9)
__device__ __forceinline__ float iou_rn(float ax1, float ay1, float ax2, float ay2, float areaA,
                                        float bx1, float by1, float bx2, float by2, float areaB) {
    float ltx = fmaxf(ax1, bx1), lty = fmaxf(ay1, by1);
    float rbx = fminf(ax2, bx2), rby = fminf(ay2, by2);
    float ww = fmaxf(__fsub_rn(rbx, ltx), 0.0f);
    float hh = fmaxf(__fsub_rn(rby, lty), 0.0f);
    float inter = __fmul_rn(ww, hh);
    float uni = __fadd_rn(__fsub_rn(__fadd_rn(areaA, areaB), inter), 1e-9f);
    return __fdiv_rn(inter, uni);
}

// ============================================================
// Kernel 2: one block per batch. radix-select top-1024 -> rank-sort
// -> cls recovery -> per-class greedy NMS -> cap 300 -> matching.
// ============================================================
__global__ __launch_bounds__(1024, 1) void k2_select(
    const float* __restrict__ preds,
    const float* __restrict__ gt_boxes,
    const int*   __restrict__ gt_cls,
    const int*   __restrict__ gt_mask,
    const int*   __restrict__ cat_to_super,
    float*       __restrict__ out)
{
    __shared__ unsigned long long s_key[Kn];
    __shared__ float s_conf[Kn];
    __shared__ int   s_anchor[Kn];
    __shared__ float s_x1[Kn], s_y1[Kn], s_x2[Kn], s_y2[Kn];
    __shared__ int   s_cls[Kn];
    __shared__ unsigned char  s_keep[Kn];
    __shared__ unsigned short s_list[Kn];
    __shared__ int   s_scan[Kn];
    __shared__ unsigned int s_hist[256];
    __shared__ int   s_off[NCn + 1];
    __shared__ unsigned long long sh_prefix;
    __shared__ int sh_r, sh_cnt;
    __shared__ float s_gtb[Gn][4];
    __shared__ int   s_gtc[Gn], s_gtm[Gn], s_hit[Gn];
    __shared__ float s_biou[Gn], s_bconf[Gn];

    const int b = blockIdx.x;
    const int tid = threadIdx.x;
    const int lane = tid & 31;
    const int wid = tid >> 5;
    const unsigned long long* keys = g_keys + (size_t)b * An;

    // ---- load GT ----
    if (tid < Gn) {
        s_gtc[tid] = gt_cls[b * Gn + tid];
        s_gtm[tid] = gt_mask[b * Gn + tid];
#pragma unroll
        for (int k = 0; k < 4; ++k)
            s_gtb[tid][k] = gt_boxes[(size_t)(b * Gn + tid) * 4 + k];
    }
    if (tid == 0) { sh_prefix = 0ull; sh_r = Kn - 1; sh_cnt = 0; }

    // ---- Phase A: 8-pass MSB radix select of the 1024th-largest key ----
    unsigned long long mask_hi = 0ull;
    for (int pass = 0; pass < 8; ++pass) {
        int shift = 56 - 8 * pass;
        if (tid < 256) s_hist[tid] = 0u;
        __syncthreads();
        unsigned long long pref = sh_prefix;
        for (int it = 0; it < 9; ++it) {
            int idx = tid + it * 1024;
            int dig = 256;
            if (idx < An) {
                unsigned long long k = keys[idx];
                if ((k & mask_hi) == pref) dig = (int)((k >> shift) & 255ull);
            }
            unsigned m = __match_any_sync(0xFFFFFFFFu, dig);
            int leader = __ffs(m) - 1;
            if (lane == leader && dig < 256)
                atomicAdd(&s_hist[dig], (unsigned)__popc(m));
        }
        __syncthreads();
        if (tid == 0) {
            int r = sh_r;
            int d = 255;
            for (; d > 0; --d) {
                int c = (int)s_hist[d];
                if (r < c) break;
                r -= c;
            }
            sh_r = r;
            sh_prefix = pref | ((unsigned long long)d << shift);
        }
        mask_hi |= (0xFFull << shift);
        __syncthreads();
    }
    const unsigned long long T = sh_prefix;

    // ---- Phase B: compact keys >= T (exactly 1024; keys are unique) ----
    for (int it = 0; it < 9; ++it) {
        int idx = tid + it * 1024;
        unsigned long long k = (idx < An) ? keys[idx] : 0ull;
        bool sel = (idx < An) && (k >= T);
        unsigned bal = __ballot_sync(0xFFFFFFFFu, sel);
        if (bal) {
            int leader = __ffs(bal) - 1;
            int basep = 0;
            if (lane == leader) basep = atomicAdd(&sh_cnt, __popc(bal));
            basep = __shfl_sync(0xFFFFFFFFu, basep, leader);
            if (sel) {
                int p = basep + __popc(bal & ((1u << lane) - 1u));
                if (p < Kn) s_key[p] = k;
            }
        }
    }
    __syncthreads();

    // ---- rank-sort the 1024 selected (descending conf, index asc) ----
    {
        unsigned long long myk = s_key[tid];
        int rank = 0;
#pragma unroll 8
        for (int j = 0; j < Kn; ++j) rank += (s_key[j] > myk) ? 1 : 0;
        s_conf[rank]   = __uint_as_float((unsigned)(myk >> 32));
        s_anchor[rank] = (int)(0xFFFFFFFFu - (unsigned)(myk & 0xFFFFFFFFull));
    }
    __syncthreads();

    // ---- gather boxes ----
    {
        int a = s_anchor[tid];
        float4 bx = g_boxes[(size_t)b * An + a];
        s_x1[tid] = bx.x; s_y1[tid] = bx.y; s_x2[tid] = bx.z; s_y2[tid] = bx.w;
        s_cls[tid] = 1000;  // init for atomicMin recovery
    }
    __syncthreads();

    // ---- cls recovery: first class whose score equals conf ----
    for (int z = tid; z < Kn * NCn; z += 1024) {
        int i = z / NCn;
        int c = z - i * NCn;
        int a = s_anchor[i];
        float v = __ldg(preds + ((size_t)b * (4 + NCn) + 4 + c) * An + a);
        if (v == s_conf[i]) atomicMin(&s_cls[i], c);
    }
    __syncthreads();
    if (s_cls[tid] >= NCn) s_cls[tid] = 0;  // conf==0 corner; never kept
    if (tid < 256) s_hist[tid] = 0u;
    s_keep[tid] = 0;
    __syncthreads();

    // ---- class histogram + stable bucket placement ----
    int myc = s_cls[tid];
    atomicAdd(&s_hist[myc], 1u);
    __syncthreads();
    if (tid == 0) {
        int acc = 0;
        for (int c = 0; c < NCn; ++c) { s_off[c] = acc; acc += (int)s_hist[c]; }
        s_off[NCn] = acc;
    }
    __syncthreads();
    {
        int crank = 0;
        for (int j = 0; j < tid; ++j) crank += (s_cls[j] == myc) ? 1 : 0;
        s_list[s_off[myc] + crank] = (unsigned short)tid;
    }
    __syncthreads();

    // ---- per-class greedy NMS (cross-class IoU is exactly 0) ----
    if (tid < NCn) {
        const int c = tid;
        const int beg = s_off[c], end = s_off[c + 1];
        const float sa = __fmul_rn((float)c, 7680.0f);
        for (int m = beg; m < end; ++m) {
            int i = s_list[m];
            unsigned char kf = 0;
            if (s_conf[i] > 0.0f) {
                float ax1 = __fadd_rn(s_x1[i], sa), ay1 = __fadd_rn(s_y1[i], sa);
                float ax2 = __fadd_rn(s_x2[i], sa), ay2 = __fadd_rn(s_y2[i], sa);
                float areaA = __fmul_rn(__fsub_rn(ax2, ax1), __fsub_rn(ay2, ay1));
                kf = 1;
                for (int mm = beg; mm < m; ++mm) {
                    int j = s_list[mm];
                    if (!s_keep[j]) continue;
                    float bx1 = __fadd_rn(s_x1[j], sa), by1 = __fadd_rn(s_y1[j], sa);
                    float bx2 = __fadd_rn(s_x2[j], sa), by2 = __fadd_rn(s_y2[j], sa);
                    float areaB = __fmul_rn(__fsub_rn(bx2, bx1), __fsub_rn(by2, by1));
                    if (iou_rn(ax1, ay1, ax2, ay2, areaA, bx1, by1, bx2, by2, areaB) > 0.45f) {
                        kf = 0; break;
                    }
                }
            }
            s_keep[i] = kf;
        }
    }
    __syncthreads();

    // ---- inclusive scan of keep, cap at 300, build pv ----
    s_scan[tid] = (int)s_keep[tid];
    __syncthreads();
    for (int off = 1; off < Kn; off <<= 1) {
        int v = s_scan[tid];
        if (tid >= off) v += s_scan[tid - off];
        __syncthreads();
        s_scan[tid] = v;
        __syncthreads();
    }
    int pv = (s_keep[tid] && s_scan[tid] <= MAXDET && s_conf[tid] > 0.5f) ? 1 : 0;
    int n_pred = __syncthreads_count(pv);
    s_keep[tid] = (unsigned char)pv;
    __syncthreads();

    // ---- matching: one warp per GT ----
    {
        const int g = wid;
        float gx1 = s_gtb[g][0], gy1 = s_gtb[g][1], gx2 = s_gtb[g][2], gy2 = s_gtb[g][3];
        float areaG = __fmul_rn(__fsub_rn(gx2, gx1), __fsub_rn(gy2, gy1));
        int gc = s_gtc[g];
        float best = -__int_as_float(0x7f800000);  // -inf
        int bidx = 0;
        for (int i = lane; i < Kn; i += 32) {
            float v = -1.0f;
            if (s_keep[i] && s_cls[i] == gc) {
                float ax1 = s_x1[i], ay1 = s_y1[i], ax2 = s_x2[i], ay2 = s_y2[i];
                float areaA = __fmul_rn(__fsub_rn(ax2, ax1), __fsub_rn(ay2, ay1));
                v = iou_rn(ax1, ay1, ax2, ay2, areaA, gx1, gy1, gx2, gy2, areaG);
            }
            if (v > best) { best = v; bidx = i; }
        }
#pragma unroll
        for (int off = 16; off > 0; off >>= 1) {
            float ov = __shfl_down_sync(0xFFFFFFFFu, best, off);
            int   oi = __shfl_down_sync(0xFFFFFFFFu, bidx, off);
            if (ov > best || (ov == best && oi < bidx)) { best = ov; bidx = oi; }
        }
        if (lane == 0) {
            s_biou[g]  = best;
            s_bconf[g] = s_conf[bidx];
            s_hit[g]   = (best > 0.6f) && (s_gtm[g] != 0);
        }
    }
    __syncthreads();

    // ---- final stats ----
    if (tid == 0) {
        float cat[NCn]; float sup[NSUPn];
        for (int c = 0; c < NCn; ++c) cat[c] = 0.f;
        for (int s = 0; s < NSUPn; ++s) sup[s] = 0.f;
        float n_gt = 0.f, n_hit = 0.f, sum_iou = 0.f, sum_conf = 0.f;
        for (int g = 0; g < Gn; ++g) {
            float gm = (s_gtm[g] != 0) ? 1.0f : 0.0f;
            n_gt += gm;
            cat[s_gtc[g]] += gm;
            sup[cat_to_super[s_gtc[g]]] += gm;
            if (s_hit[g]) { n_hit += 1.0f; sum_iou += s_biou[g]; sum_conf += s_bconf[g]; }
        }
        int mfc = 0;
        for (int c = 1; c < NCn; ++c) if (cat[c] > cat[mfc]) mfc = c;
        int mfs = 0;
        for (int s = 1; s < NSUPn; ++s) if (sup[s] > sup[mfs]) mfs = s;
        float fh = n_hit;
        float mean_iou  = __fdiv_rn(sum_iou,  fmaxf(fh, 1.0f));
        float mean_conf = (n_hit > 0.0f) ? __fdiv_rn(sum_conf, fmaxf(fh, 1.0f)) : 1.0f;
        float correct   = __fdiv_rn(fh, fmaxf(n_gt, 1.0f));
        float r0, r1, r2, r3, r4;
        if (n_gt == 0.0f) {
            if (n_pred == 0) { r0 = 1.f; r1 = 1.f; r2 = -1.f; r3 = -1.f; r4 = 1.f; }
            else             { r0 = 0.f; r1 = 1.f; r2 = -2.f; r3 = -2.f; r4 = 0.f; }
        } else {
            r0 = mean_iou; r1 = mean_conf; r2 = (float)mfc; r3 = (float)mfs; r4 = correct;
        }
        out[b * 5 + 0] = r0; out[b * 5 + 1] = r1; out[b * 5 + 2] = r2;
        out[b * 5 + 3] = r3; out[b * 5 + 4] = r4;
    }
}

extern "C" void kernel_launch(void* const* d_in, const int* in_sizes, int n_in,
                              void* d_out, int out_size) {
    const float* preds        = (const float*)d_in[0];
    const float* gt_boxes     = (const float*)d_in[1];
    const int*   gt_cls       = (const int*)d_in[2];
    const int*   gt_mask      = (const int*)d_in[3];
    const int*   cat_to_super = (const int*)d_in[4];
    float* out = (float*)d_out;

    int tot = Bn * (An / 4);
    k1_scores<<<(tot + 255) / 256, 256>>>(preds);
    k2_select<<<Bn, 1024>>>(preds, gt_boxes, gt_cls, gt_mask, cat_to_super, out);
}

// round 2
// speedup vs baseline: 1.5565x; 1.5565x over previous
#include <cuda_runtime.h>
#include <cstdint>

#define Bn 32
#define An 8400
#define NCn 80
#define Kn 1024
#define Gn 32
#define NSUPn 16
#define MAXDET 300

// -------- scratch (no allocs allowed) --------
// key = (conf_bits << 32) | (((0x3FFF - a) << 3) | group)
__device__ unsigned long long g_keys[Bn * An];
__device__ float4             g_boxes[Bn * An];

// ============================================================
// Kernel 1: decode boxes + conf = max(scores) with 8-group tracking.
// Groups 0-3 on fma pipe (FMNMX), 4-7 on alu pipe (IMNMX on bits,
// valid since scores >= 0). Group id packed into key low bits so the
// cls recovery in k2 only reads 10 classes per selected anchor.
// ============================================================
__global__ void k1_scores(const float* __restrict__ preds) {
    const int APQ = An / 4;
    int t = blockIdx.x * blockDim.x + threadIdx.x;
    if (t >= Bn * APQ) return;
    int b  = t / APQ;
    int a4 = (t - b * APQ) * 4;
    const float* base = preds + (size_t)b * (4 + NCn) * An;

    float4 cx = *(const float4*)(base + (size_t)0 * An + a4);
    float4 cy = *(const float4*)(base + (size_t)1 * An + a4);
    float4 w  = *(const float4*)(base + (size_t)2 * An + a4);
    float4 h  = *(const float4*)(base + (size_t)3 * An + a4);

    float    fA[4][4];
    unsigned iA[4][4];
#pragma unroll
    for (int g = 0; g < 4; ++g)
#pragma unroll
        for (int k = 0; k < 4; ++k) { fA[g][k] = 0.f; iA[g][k] = 0u; }

#pragma unroll
    for (int j = 0; j < 40; ++j) {
        float4 s = *(const float4*)(base + (size_t)(4 + j) * An + a4);
        int g = j / 10;
        fA[g][0] = fmaxf(fA[g][0], s.x);
        fA[g][1] = fmaxf(fA[g][1], s.y);
        fA[g][2] = fmaxf(fA[g][2], s.z);
        fA[g][3] = fmaxf(fA[g][3], s.w);
    }
#pragma unroll
    for (int j = 40; j < 80; ++j) {
        float4 s = *(const float4*)(base + (size_t)(4 + j) * An + a4);
        int g = j / 10 - 4;
        iA[g][0] = max(iA[g][0], __float_as_uint(s.x));
        iA[g][1] = max(iA[g][1], __float_as_uint(s.y));
        iA[g][2] = max(iA[g][2], __float_as_uint(s.z));
        iA[g][3] = max(iA[g][3], __float_as_uint(s.w));
    }

    float cxa[4] = {cx.x, cx.y, cx.z, cx.w};
    float cya[4] = {cy.x, cy.y, cy.z, cy.w};
    float wa[4]  = {w.x,  w.y,  w.z,  w.w};
    float ha[4]  = {h.x,  h.y,  h.z,  h.w};

#pragma unroll
    for (int k = 0; k < 4; ++k) {
        int a = a4 + k;
        float m01 = fmaxf(fA[0][k], fA[1][k]);
        float m23 = fmaxf(fA[2][k], fA[3][k]);
        float mF  = fmaxf(m01, m23);
        float f4v = __uint_as_float(iA[0][k]);
        float f5v = __uint_as_float(iA[1][k]);
        float f6v = __uint_as_float(iA[2][k]);
        float f7v = __uint_as_float(iA[3][k]);
        float m45 = fmaxf(f4v, f5v);
        float m67 = fmaxf(f6v, f7v);
        float mI  = fmaxf(m45, m67);
        float m   = fmaxf(mF, mI);
        unsigned mb = __float_as_uint(m);
        int g = (__float_as_uint(fA[0][k]) == mb) ? 0 :
                (__float_as_uint(fA[1][k]) == mb) ? 1 :
                (__float_as_uint(fA[2][k]) == mb) ? 2 :
                (__float_as_uint(fA[3][k]) == mb) ? 3 :
                (iA[0][k] == mb) ? 4 :
                (iA[1][k] == mb) ? 5 :
                (iA[2][k] == mb) ? 6 : 7;
        float tc = (m > 0.25f) ? m : 0.0f;
        unsigned low = ((0x3FFFu - (unsigned)a) << 3) | (unsigned)g;
        g_keys[(size_t)b * An + a] =
            ((unsigned long long)__float_as_uint(tc) << 32) | (unsigned long long)low;

        float hw = __fmul_rn(wa[k], 0.5f);
        float hh = __fmul_rn(ha[k], 0.5f);
        g_boxes[(size_t)b * An + a] = make_float4(
            __fsub_rn(cxa[k], hw), __fsub_rn(cya[k], hh),
            __fadd_rn(cxa[k], hw), __fadd_rn(cya[k], hh));
    }
}

// exact-rounded IoU matching the reference formula
__device__ __forceinline__ float iou_rn(float ax1, float ay1, float ax2, float ay2, float areaA,
                                        float bx1, float by1, float bx2, float by2, float areaB) {
    float ltx = fmaxf(ax1, bx1), lty = fmaxf(ay1, by1);
    float rbx = fminf(ax2, bx2), rby = fminf(ay2, by2);
    float ww = fmaxf(__fsub_rn(rbx, ltx), 0.0f);
    float hh = fmaxf(__fsub_rn(rby, lty), 0.0f);
    float inter = __fmul_rn(ww, hh);
    float uni = __fadd_rn(__fsub_rn(__fadd_rn(areaA, areaB), inter), 1e-9f);
    return __fdiv_rn(inter, uni);
}

__device__ __forceinline__ int warp_incl_scan(int x, int lane) {
#pragma unroll
    for (int off = 1; off < 32; off <<= 1) {
        int y = __shfl_up_sync(0xFFFFFFFFu, x, off);
        if (lane >= off) x += y;
    }
    return x;
}

// ============================================================
// Kernel 2: one block per batch.
// ============================================================
__global__ __launch_bounds__(1024, 1) void k2_select(
    const float* __restrict__ preds,
    const float* __restrict__ gt_boxes,
    const int*   __restrict__ gt_cls,
    const int*   __restrict__ gt_mask,
    const int*   __restrict__ cat_to_super,
    float*       __restrict__ out)
{
    __shared__ union {
        unsigned long long key[Kn];                              // select + sort phase
        struct { unsigned char wc[32][NCn]; int scan_w[32]; } p; // post phase
    } uS;
    __shared__ unsigned int s_hist[256];   // radix hist; later reused as float stats bins
    __shared__ float s_conf[Kn];
    __shared__ unsigned int s_low[Kn];
    __shared__ float s_x1[Kn], s_y1[Kn], s_x2[Kn], s_y2[Kn];
    __shared__ unsigned char s_cls[Kn], s_keep[Kn];
    __shared__ unsigned short s_list[Kn];
    __shared__ int s_off[NCn + 1];
    __shared__ unsigned long long sh_prefix;
    __shared__ int sh_r, sh_cnt;
    __shared__ float s_gtb[Gn][4];
    __shared__ int   s_gtc[Gn], s_gtm[Gn], s_hit[Gn];
    __shared__ float s_biou[Gn], s_bconf[Gn];

    const int b = blockIdx.x;
    const int tid = threadIdx.x;
    const int lane = tid & 31;
    const int wid = tid >> 5;
    const unsigned lmask_lt = (1u << lane) - 1u;
    const unsigned long long* keys = g_keys + (size_t)b * An;

    if (tid < Gn) {
        s_gtc[tid] = gt_cls[b * Gn + tid];
        s_gtm[tid] = gt_mask[b * Gn + tid];
#pragma unroll
        for (int k = 0; k < 4; ++k)
            s_gtb[tid][k] = gt_boxes[(size_t)(b * Gn + tid) * 4 + k];
    }
    if (tid == 0) { sh_prefix = 0ull; sh_r = Kn - 1; sh_cnt = 0; }

    // ---- load the batch's keys into registers (once) ----
    unsigned long long kr[9];
#pragma unroll
    for (int it = 0; it < 9; ++it) {
        int idx = tid + it * 1024;
        kr[it] = (idx < An) ? keys[idx] : 0ull;
    }
    const bool v8 = (tid < An - 8192);

    // ---- 8-pass MSB radix select, no reloads, parallel bin pick ----
    unsigned long long mask_hi = 0ull;
    for (int pass = 0; pass < 8; ++pass) {
        int shift = 56 - 8 * pass;
        if (tid < 256) s_hist[tid] = 0u;
        __syncthreads();
        unsigned long long pref = sh_prefix;
#pragma unroll
        for (int it = 0; it < 9; ++it) {
            bool valid = (it < 8) || v8;
            int dig = (valid && ((kr[it] & mask_hi) == pref))
                        ? (int)((kr[it] >> shift) & 255ull) : 256;
            unsigned m = __match_any_sync(0xFFFFFFFFu, dig);
            if (dig < 256 && (m & lmask_lt) == 0u)
                atomicAdd(&s_hist[dig], (unsigned)__popc(m));
        }
        __syncthreads();
        if (tid < 32) {
            unsigned hh[8];
#pragma unroll
            for (int j = 0; j < 8; ++j) hh[j] = s_hist[lane * 8 + j];
            unsigned suf[9]; suf[8] = 0u;
#pragma unroll
            for (int j = 7; j >= 0; --j) suf[j] = suf[j + 1] + hh[j];
            unsigned laneTot = suf[0];
            unsigned v = laneTot;
#pragma unroll
            for (int off = 1; off < 32; off <<= 1) {
                unsigned o = __shfl_down_sync(0xFFFFFFFFu, v, off);
                if (lane + off < 32) v += o;
            }
            unsigned exAbove = v - laneTot;  // sum over lanes > lane
            unsigned r = (unsigned)sh_r;
            int myd = -1; unsigned mySe = 0;
#pragma unroll
            for (int j = 0; j < 8; ++j) {
                unsigned Se = exAbove + suf[j + 1];
                if (Se <= r && r < Se + hh[j]) { myd = lane * 8 + j; mySe = Se; }
            }
            if (myd >= 0) {
                sh_prefix = pref | ((unsigned long long)myd << shift);
                sh_r = (int)(r - mySe);
            }
        }
        mask_hi |= (0xFFull << shift);
        __syncthreads();
    }
    const unsigned long long T = sh_prefix;

    // ---- compact keys >= T (exactly 1024; keys are unique) ----
#pragma unroll
    for (int it = 0; it < 9; ++it) {
        bool valid = (it < 8) || v8;
        bool sel = valid && (kr[it] >= T);
        unsigned bal = __ballot_sync(0xFFFFFFFFu, sel);
        if (bal) {
            int leader = __ffs(bal) - 1;
            int basep = 0;
            if (lane == leader) basep = atomicAdd(&sh_cnt, __popc(bal));
            basep = __shfl_sync(0xFFFFFFFFu, basep, leader);
            if (sel) {
                int p = basep + __popc(bal & lmask_lt);
                if (p < Kn) uS.key[p] = kr[it];
            }
        }
    }
    __syncthreads();

    // ---- bitonic sort, descending (unique keys -> strict total order) ----
    for (int kk = 2; kk <= Kn; kk <<= 1) {
        for (int j = kk >> 1; j > 0; j >>= 1) {
            int ixj = tid ^ j;
            if (ixj > tid) {
                unsigned long long a = uS.key[tid];
                unsigned long long c = uS.key[ixj];
                bool dec = (tid & kk) == 0;
                if ((a < c) == dec) { uS.key[tid] = c; uS.key[ixj] = a; }
            }
            __syncthreads();
        }
    }

    // ---- extract + gather boxes ----
    int my_a, my_g;
    {
        unsigned long long kk = uS.key[tid];
        float cf = __uint_as_float((unsigned)(kk >> 32));
        unsigned low = (unsigned)kk;
        s_conf[tid] = cf;
        s_low[tid] = low;
        my_a = 0x3FFF - (int)(low >> 3);
        my_g = (int)(low & 7u);
        float4 bx = g_boxes[(size_t)b * An + my_a];
        s_x1[tid] = bx.x; s_y1[tid] = bx.y; s_x2[tid] = bx.z; s_y2[tid] = bx.w;
    }
    __syncthreads();  // uS.key now dead; uS.p may be written

    // ---- cls recovery: only 10 classes of the winning group ----
    {
        float cf = s_conf[tid];
        int c0 = my_g * 10;
        const float* sp = preds + ((size_t)b * (4 + NCn) + 4 + c0) * An + my_a;
        float v[10];
#pragma unroll
        for (int j = 0; j < 10; ++j) v[j] = __ldg(sp + (size_t)j * An);
        int cls = c0;
#pragma unroll
        for (int j = 9; j >= 0; --j) if (v[j] == cf) cls = c0 + j;
        s_cls[tid] = (unsigned char)cls;
    }
    // zero per-warp class counts + keep flags
    for (int i = tid; i < 32 * NCn; i += 1024) ((unsigned char*)uS.p.wc)[i] = 0;
    s_keep[tid] = 0;
    __syncthreads();

    // ---- stable bucket placement (warp match + cross-warp prefix) ----
    int myc = (int)s_cls[tid];
    unsigned mm = __match_any_sync(0xFFFFFFFFu, myc);
    int within = __popc(mm & lmask_lt);
    if (within == 0) uS.p.wc[wid][myc] = (unsigned char)__popc(mm);
    __syncthreads();
    if (tid < NCn) {
        int t = 0;
#pragma unroll
        for (int w = 0; w < 32; ++w) t += (int)uS.p.wc[w][tid];
        s_off[tid + 1] = t;
    }
    __syncthreads();
    if (tid == 0) {
        s_off[0] = 0;
        int acc = 0;
        for (int c = 1; c <= NCn; ++c) { acc += s_off[c]; s_off[c] = acc; }
    }
    __syncthreads();
    {
        int cross = 0;
        for (int w = 0; w < wid; ++w) cross += (int)uS.p.wc[w][myc];
        s_list[s_off[myc] + cross + within] = (unsigned short)tid;
    }
    __syncthreads();

    // ---- per-class greedy NMS (cross-class IoU exactly 0 after shift) ----
    if (tid < NCn) {
        const int c = tid;
        const int beg = s_off[c], end = s_off[c + 1];
        const float sa = __fmul_rn((float)c, 7680.0f);
        for (int m = beg; m < end; ++m) {
            int i = s_list[m];
            unsigned char kf = 0;
            if (s_conf[i] > 0.0f) {
                float ax1 = __fadd_rn(s_x1[i], sa), ay1 = __fadd_rn(s_y1[i], sa);
                float ax2 = __fadd_rn(s_x2[i], sa), ay2 = __fadd_rn(s_y2[i], sa);
                float areaA = __fmul_rn(__fsub_rn(ax2, ax1), __fsub_rn(ay2, ay1));
                kf = 1;
                for (int mm2 = beg; mm2 < m; ++mm2) {
                    int j = s_list[mm2];
                    if (!s_keep[j]) continue;
                    float bx1 = __fadd_rn(s_x1[j], sa), by1 = __fadd_rn(s_y1[j], sa);
                    float bx2 = __fadd_rn(s_x2[j], sa), by2 = __fadd_rn(s_y2[j], sa);
                    float areaB = __fmul_rn(__fsub_rn(bx2, bx1), __fsub_rn(by2, by1));
                    if (iou_rn(ax1, ay1, ax2, ay2, areaA, bx1, by1, bx2, by2, areaB) > 0.45f) {
                        kf = 0; break;
                    }
                }
            }
            s_keep[i] = kf;
        }
    }
    __syncthreads();

    // ---- hierarchical inclusive scan of keep; cap 300; build pv ----
    int inc = warp_incl_scan((int)s_keep[tid], lane);
    if (lane == 31) uS.p.scan_w[wid] = inc;
    __syncthreads();
    if (tid < 32) uS.p.scan_w[tid] = warp_incl_scan(uS.p.scan_w[tid], tid);
    __syncthreads();
    int csum = inc + (wid > 0 ? uS.p.scan_w[wid - 1] : 0);
    int pv = (s_keep[tid] && csum <= MAXDET && s_conf[tid] > 0.5f) ? 1 : 0;
    int n_pred = __syncthreads_count(pv);
    s_keep[tid] = (unsigned char)pv;
    __syncthreads();

    // ---- matching: one warp per GT ----
    {
        const int g = wid;
        float gx1 = s_gtb[g][0], gy1 = s_gtb[g][1], gx2 = s_gtb[g][2], gy2 = s_gtb[g][3];
        float areaG = __fmul_rn(__fsub_rn(gx2, gx1), __fsub_rn(gy2, gy1));
        int gc = s_gtc[g];
        float best = -__int_as_float(0x7f800000);
        int bidx = 0;
        for (int i = lane; i < Kn; i += 32) {
            float v = -1.0f;
            if (s_keep[i] && (int)s_cls[i] == gc) {
                float ax1 = s_x1[i], ay1 = s_y1[i], ax2 = s_x2[i], ay2 = s_y2[i];
                float areaA = __fmul_rn(__fsub_rn(ax2, ax1), __fsub_rn(ay2, ay1));
                v = iou_rn(ax1, ay1, ax2, ay2, areaA, gx1, gy1, gx2, gy2, areaG);
            }
            if (v > best) { best = v; bidx = i; }
        }
#pragma unroll
        for (int off = 16; off > 0; off >>= 1) {
            float ov = __shfl_down_sync(0xFFFFFFFFu, best, off);
            int   oi = __shfl_down_sync(0xFFFFFFFFu, bidx, off);
            if (ov > best || (ov == best && oi < bidx)) { best = ov; bidx = oi; }
        }
        if (lane == 0) {
            s_biou[g]  = best;
            s_bconf[g] = s_conf[bidx];
            s_hit[g]   = (best > 0.6f) && (s_gtm[g] != 0);
        }
    }
    __syncthreads();

    // ---- final stats (warp 0; smem bins reuse s_hist) ----
    float* bins = (float*)s_hist;  // [0..79] cat, [80..95] sup
    if (tid < 96) bins[tid] = 0.0f;
    __syncthreads();
    if (tid < 32) {
        int g = tid;
        float gm = (s_gtm[g] != 0) ? 1.0f : 0.0f;
        int gc = s_gtc[g];
        atomicAdd(&bins[gc], gm);
        atomicAdd(&bins[80 + cat_to_super[gc]], gm);
        float hi = s_hit[g] ? 1.0f : 0.0f;
        float n_gt = gm, n_hit = hi;
        float s_iou = hi * s_biou[g];
        float s_cf  = hi * s_bconf[g];
#pragma unroll
        for (int off = 16; off > 0; off >>= 1) {
            n_gt  += __shfl_down_sync(0xFFFFFFFFu, n_gt,  off);
            n_hit += __shfl_down_sync(0xFFFFFFFFu, n_hit, off);
            s_iou += __shfl_down_sync(0xFFFFFFFFu, s_iou, off);
            s_cf  += __shfl_down_sync(0xFFFFFFFFu, s_cf,  off);
        }
        if (tid == 0) {
            int mfc = 0;
            for (int c = 1; c < NCn; ++c) if (bins[c] > bins[mfc]) mfc = c;
            int mfs = 0;
            for (int s = 1; s < NSUPn; ++s) if (bins[80 + s] > bins[80 + mfs]) mfs = s;
            float fh = n_hit;
            float mean_iou  = __fdiv_rn(s_iou, fmaxf(fh, 1.0f));
            float mean_conf = (n_hit > 0.0f) ? __fdiv_rn(s_cf, fmaxf(fh, 1.0f)) : 1.0f;
            float correct   = __fdiv_rn(fh, fmaxf(n_gt, 1.0f));
            float r0, r1, r2, r3, r4;
            if (n_gt == 0.0f) {
                if (n_pred == 0) { r0 = 1.f; r1 = 1.f; r2 = -1.f; r3 = -1.f; r4 = 1.f; }
                else             { r0 = 0.f; r1 = 1.f; r2 = -2.f; r3 = -2.f; r4 = 0.f; }
            } else {
                r0 = mean_iou; r1 = mean_conf; r2 = (float)mfc; r3 = (float)mfs; r4 = correct;
            }
            out[b * 5 + 0] = r0; out[b * 5 + 1] = r1; out[b * 5 + 2] = r2;
            out[b * 5 + 3] = r3; out[b * 5 + 4] = r4;
        }
    }
}

extern "C" void kernel_launch(void* const* d_in, const int* in_sizes, int n_in,
                              void* d_out, int out_size) {
    const float* preds        = (const float*)d_in[0];
    const float* gt_boxes     = (const float*)d_in[1];
    const int*   gt_cls       = (const int*)d_in[2];
    const int*   gt_mask      = (const int*)d_in[3];
    const int*   cat_to_super = (const int*)d_in[4];
    float* out = (float*)d_out;

    int tot = Bn * (An / 4);
    k1_scores<<<(tot + 255) / 256, 256>>>(preds);
    k2_select<<<Bn, 1024>>>(preds, gt_boxes, gt_cls, gt_mask, cat_to_super, out);
}

// round 3
// speedup vs baseline: 2.7690x; 1.7790x over previous
#include <cuda_runtime.h>
#include <cstdint>

#define Bn 32
#define An 8400
#define NCn 80
#define Kn 1024
#define Gn 32
#define NSUPn 16
#define MAXDET 300

// -------- scratch (no allocs allowed) --------
// key = (conf_bits << 32) | (((0x3FFF - a) << 3) | group)
__device__ unsigned long long g_keys[Bn * An];
__device__ float4             g_boxes[Bn * An];

// ============================================================
// Kernel 1: decode + conf=max(scores), 8-group tracking (fma+alu pipes).
// ============================================================
__global__ void k1_scores(const float* __restrict__ preds) {
    const int APQ = An / 4;
    int t = blockIdx.x * blockDim.x + threadIdx.x;
    if (t >= Bn * APQ) return;
    int b  = t / APQ;
    int a4 = (t - b * APQ) * 4;
    const float* base = preds + (size_t)b * (4 + NCn) * An;

    float4 cx = *(const float4*)(base + (size_t)0 * An + a4);
    float4 cy = *(const float4*)(base + (size_t)1 * An + a4);
    float4 w  = *(const float4*)(base + (size_t)2 * An + a4);
    float4 h  = *(const float4*)(base + (size_t)3 * An + a4);

    float    fA[4][4];
    unsigned iA[4][4];
#pragma unroll
    for (int g = 0; g < 4; ++g)
#pragma unroll
        for (int k = 0; k < 4; ++k) { fA[g][k] = 0.f; iA[g][k] = 0u; }

#pragma unroll
    for (int j = 0; j < 40; ++j) {
        float4 s = *(const float4*)(base + (size_t)(4 + j) * An + a4);
        int g = j / 10;
        fA[g][0] = fmaxf(fA[g][0], s.x);
        fA[g][1] = fmaxf(fA[g][1], s.y);
        fA[g][2] = fmaxf(fA[g][2], s.z);
        fA[g][3] = fmaxf(fA[g][3], s.w);
    }
#pragma unroll
    for (int j = 40; j < 80; ++j) {
        float4 s = *(const float4*)(base + (size_t)(4 + j) * An + a4);
        int g = j / 10 - 4;
        iA[g][0] = max(iA[g][0], __float_as_uint(s.x));
        iA[g][1] = max(iA[g][1], __float_as_uint(s.y));
        iA[g][2] = max(iA[g][2], __float_as_uint(s.z));
        iA[g][3] = max(iA[g][3], __float_as_uint(s.w));
    }

    float cxa[4] = {cx.x, cx.y, cx.z, cx.w};
    float cya[4] = {cy.x, cy.y, cy.z, cy.w};
    float wa[4]  = {w.x,  w.y,  w.z,  w.w};
    float ha[4]  = {h.x,  h.y,  h.z,  h.w};

#pragma unroll
    for (int k = 0; k < 4; ++k) {
        int a = a4 + k;
        float m01 = fmaxf(fA[0][k], fA[1][k]);
        float m23 = fmaxf(fA[2][k], fA[3][k]);
        float mF  = fmaxf(m01, m23);
        float m45 = fmaxf(__uint_as_float(iA[0][k]), __uint_as_float(iA[1][k]));
        float m67 = fmaxf(__uint_as_float(iA[2][k]), __uint_as_float(iA[3][k]));
        float m   = fmaxf(mF, fmaxf(m45, m67));
        unsigned mb = __float_as_uint(m);
        int g = (__float_as_uint(fA[0][k]) == mb) ? 0 :
                (__float_as_uint(fA[1][k]) == mb) ? 1 :
                (__float_as_uint(fA[2][k]) == mb) ? 2 :
                (__float_as_uint(fA[3][k]) == mb) ? 3 :
                (iA[0][k] == mb) ? 4 :
                (iA[1][k] == mb) ? 5 :
                (iA[2][k] == mb) ? 6 : 7;
        float tc = (m > 0.25f) ? m : 0.0f;
        unsigned low = ((0x3FFFu - (unsigned)a) << 3) | (unsigned)g;
        g_keys[(size_t)b * An + a] =
            ((unsigned long long)__float_as_uint(tc) << 32) | (unsigned long long)low;

        float hw = __fmul_rn(wa[k], 0.5f);
        float hh = __fmul_rn(ha[k], 0.5f);
        g_boxes[(size_t)b * An + a] = make_float4(
            __fsub_rn(cxa[k], hw), __fsub_rn(cya[k], hh),
            __fadd_rn(cxa[k], hw), __fadd_rn(cya[k], hh));
    }
}

__device__ __forceinline__ float iou_rn(float ax1, float ay1, float ax2, float ay2, float areaA,
                                        float bx1, float by1, float bx2, float by2, float areaB) {
    float ltx = fmaxf(ax1, bx1), lty = fmaxf(ay1, by1);
    float rbx = fminf(ax2, bx2), rby = fminf(ay2, by2);
    float ww = fmaxf(__fsub_rn(rbx, ltx), 0.0f);
    float hh = fmaxf(__fsub_rn(rby, lty), 0.0f);
    float inter = __fmul_rn(ww, hh);
    float uni = __fadd_rn(__fsub_rn(__fadd_rn(areaA, areaB), inter), 1e-9f);
    return __fdiv_rn(inter, uni);
}

__device__ __forceinline__ int warp_incl_scan(int x, int lane) {
#pragma unroll
    for (int off = 1; off < 32; off <<= 1) {
        int y = __shfl_up_sync(0xFFFFFFFFu, x, off);
        if (lane >= off) x += y;
    }
    return x;
}

// ============================================================
// Kernel 2: one block per batch.
// ============================================================
__global__ __launch_bounds__(1024, 1) void k2_select(
    const float* __restrict__ preds,
    const float* __restrict__ gt_boxes,
    const int*   __restrict__ gt_cls,
    const int*   __restrict__ gt_mask,
    const int*   __restrict__ cat_to_super,
    float*       __restrict__ out)
{
    __shared__ union {
        unsigned long long key[Kn];
        struct { unsigned char wc[32][NCn]; int scan_w[32]; } p;
    } uS;
    __shared__ unsigned int s_hist4[4][256];   // radix hists; later float stats bins
    __shared__ float s_conf[Kn];
    __shared__ float s_x1[Kn], s_y1[Kn], s_x2[Kn], s_y2[Kn];
    __shared__ unsigned char s_cls[Kn], s_keep[Kn];
    __shared__ unsigned short s_list[Kn];
    __shared__ int s_off[NCn + 1];
    __shared__ unsigned sh_pfx;
    __shared__ int sh_r, sh_cnt, sh_c, sh_tot;
    __shared__ float s_gtb[Gn][4];
    __shared__ int   s_gtc[Gn], s_gtm[Gn], s_hit[Gn];
    __shared__ float s_biou[Gn], s_bconf[Gn];

    const int b = blockIdx.x;
    const int tid = threadIdx.x;
    const int lane = tid & 31;
    const int wid = tid >> 5;
    const unsigned lmask_lt = (1u << lane) - 1u;
    const unsigned long long* keys = g_keys + (size_t)b * An;

    if (tid < Gn) {
        s_gtc[tid] = gt_cls[b * Gn + tid];
        s_gtm[tid] = gt_mask[b * Gn + tid];
#pragma unroll
        for (int k = 0; k < 4; ++k)
            s_gtb[tid][k] = gt_boxes[(size_t)(b * Gn + tid) * 4 + k];
    }
    if (tid == 0) { sh_pfx = 0u; sh_r = Kn - 1; sh_cnt = 0; sh_tot = 0; sh_c = 0; }

    // ---- load the conf (high) words into registers ----
    unsigned hr[9];
#pragma unroll
    for (int it = 0; it < 9; ++it) {
        int idx = tid + it * 1024;
        hr[it] = (idx < An) ? (unsigned)(keys[idx] >> 32) : 0u;
    }
    const bool v8 = (tid < An - 8192);

    // ---- 4-pass radix select on the 32-bit conf word ----
    unsigned mask32 = 0u;
    for (int pass = 0; pass < 4; ++pass) {
        int shift = 24 - 8 * pass;
        ((unsigned*)s_hist4)[tid] = 0u;
        __syncthreads();
        unsigned pref = sh_pfx;
        const int hc = wid & 3;
#pragma unroll
        for (int it = 0; it < 9; ++it) {
            bool valid = (it < 8) || v8;
            int dig = (valid && ((hr[it] & mask32) == pref))
                        ? (int)((hr[it] >> shift) & 255u) : 256;
            unsigned m = __match_any_sync(0xFFFFFFFFu, dig);
            if (dig < 256 && (m & lmask_lt) == 0u)
                atomicAdd(&s_hist4[hc][dig], (unsigned)__popc(m));
        }
        __syncthreads();
        if (tid < 32) {
            unsigned hh[8];
#pragma unroll
            for (int j = 0; j < 8; ++j)
                hh[j] = s_hist4[0][lane * 8 + j] + s_hist4[1][lane * 8 + j]
                      + s_hist4[2][lane * 8 + j] + s_hist4[3][lane * 8 + j];
            unsigned suf[9]; suf[8] = 0u;
#pragma unroll
            for (int j = 7; j >= 0; --j) suf[j] = suf[j + 1] + hh[j];
            unsigned laneTot = suf[0];
            unsigned v = laneTot;
#pragma unroll
            for (int off = 1; off < 32; off <<= 1) {
                unsigned o = __shfl_down_sync(0xFFFFFFFFu, v, off);
                if (lane + off < 32) v += o;
            }
            unsigned exAbove = v - laneTot;
            unsigned r = (unsigned)sh_r;
#pragma unroll
            for (int j = 0; j < 8; ++j) {
                unsigned Se = exAbove + suf[j + 1];
                if (Se <= r && r < Se + hh[j]) {
                    sh_pfx = pref | ((unsigned)(lane * 8 + j) << shift);
                    sh_r = (int)(r - Se);
                    if (pass == 3) sh_c = (int)hh[j];
                }
            }
        }
        mask32 |= (0xFFu << shift);
        __syncthreads();
    }
    const unsigned pfx = sh_pfx;
    const int r_fin = sh_r;
    const bool tie = (sh_c != r_fin + 1);

    // ---- compact top-1024 (common path: conf word strictly determines) ----
    if (!tie) {
#pragma unroll
        for (int it = 0; it < 9; ++it) {
            bool valid = (it < 8) || v8;
            bool sel = valid && (hr[it] >= pfx);
            unsigned bal = __ballot_sync(0xFFFFFFFFu, sel);
            if (bal) {
                int leader = __ffs(bal) - 1;
                int basep = 0;
                if (lane == leader) basep = atomicAdd(&sh_cnt, __popc(bal));
                basep = __shfl_sync(0xFFFFFFFFu, basep, leader);
                if (sel) {
                    int p = basep + __popc(bal & lmask_lt);
                    if (p < Kn) uS.key[p] = keys[tid + it * 1024];
                }
            }
        }
    } else {
        // rare: conf-word tie at the boundary -> exact low-word threshold
        unsigned lr[9];
#pragma unroll
        for (int it = 0; it < 9; ++it) {
            int idx = tid + it * 1024;
            lr[it] = (idx < An) ? (unsigned)keys[idx] : 0u;
        }
        unsigned T_low = 0u;
        for (int bit = 31; bit >= 0; --bit) {
            unsigned t2 = T_low | (1u << bit);
            int cnt = 0;
#pragma unroll
            for (int it = 0; it < 9; ++it) {
                bool valid = (it < 8) || v8;
                if (valid && hr[it] == pfx && lr[it] >= t2) cnt++;
            }
#pragma unroll
            for (int off = 16; off > 0; off >>= 1)
                cnt += __shfl_down_sync(0xFFFFFFFFu, cnt, off);
            if (lane == 0 && cnt) atomicAdd(&sh_tot, cnt);
            __syncthreads();
            int total = sh_tot;
            __syncthreads();
            if (tid == 0) sh_tot = 0;
            __syncthreads();
            if (total >= r_fin + 1) T_low = t2;
        }
#pragma unroll
        for (int it = 0; it < 9; ++it) {
            bool valid = (it < 8) || v8;
            bool sel = valid && ((hr[it] > pfx) || (hr[it] == pfx && lr[it] >= T_low));
            unsigned bal = __ballot_sync(0xFFFFFFFFu, sel);
            if (bal) {
                int leader = __ffs(bal) - 1;
                int basep = 0;
                if (lane == leader) basep = atomicAdd(&sh_cnt, __popc(bal));
                basep = __shfl_sync(0xFFFFFFFFu, basep, leader);
                if (sel) {
                    int p = basep + __popc(bal & lmask_lt);
                    if (p < Kn) uS.key[p] = keys[tid + it * 1024];
                }
            }
        }
    }
    __syncthreads();

    // ---- hybrid bitonic sort (descending): regs + shfl, smem only for j>=32 ----
    unsigned long long v = uS.key[tid];
    for (int kk = 2; kk <= Kn; kk <<= 1) {
        bool dirDesc = ((tid & kk) == 0);
        for (int j = kk >> 1; j > 0; j >>= 1) {
            unsigned long long pv;
            if (j >= 32) {
                __syncthreads();
                uS.key[tid] = v;
                __syncthreads();
                pv = uS.key[tid ^ j];
            } else {
                pv = __shfl_xor_sync(0xFFFFFFFFu, v, j);
            }
            bool iLower = (tid & j) == 0;
            bool takeMax = (iLower == dirDesc);
            bool pGreater = (pv > v);
            if (pGreater == takeMax) v = pv;
        }
    }
    __syncthreads();   // uS.key dead; union repurposed below

    // ---- extract + gather boxes (v = tid-th key in descending order) ----
    int my_a, my_g;
    {
        float cf = __uint_as_float((unsigned)(v >> 32));
        unsigned low = (unsigned)v;
        s_conf[tid] = cf;
        my_a = 0x3FFF - (int)(low >> 3);
        my_g = (int)(low & 7u);
        float4 bx = g_boxes[(size_t)b * An + my_a];
        s_x1[tid] = bx.x; s_y1[tid] = bx.y; s_x2[tid] = bx.z; s_y2[tid] = bx.w;
    }

    // ---- cls recovery: only the 10 classes of the winning group ----
    {
        float cf = __uint_as_float((unsigned)(v >> 32));
        int c0 = my_g * 10;
        const float* sp = preds + ((size_t)b * (4 + NCn) + 4 + c0) * An + my_a;
        float vv[10];
#pragma unroll
        for (int j = 0; j < 10; ++j) vv[j] = __ldg(sp + (size_t)j * An);
        int cls = c0;
#pragma unroll
        for (int j = 9; j >= 0; --j) if (vv[j] == cf) cls = c0 + j;
        s_cls[tid] = (unsigned char)cls;
    }
    for (int i = tid; i < 32 * NCn; i += 1024) ((unsigned char*)uS.p.wc)[i] = 0;
    s_keep[tid] = 0;
    __syncthreads();

    // ---- stable class-bucket placement ----
    int myc = (int)s_cls[tid];
    unsigned mm = __match_any_sync(0xFFFFFFFFu, myc);
    int within = __popc(mm & lmask_lt);
    if (within == 0) uS.p.wc[wid][myc] = (unsigned char)__popc(mm);
    __syncthreads();
    if (tid < NCn) {
        int t = 0;
#pragma unroll
        for (int w = 0; w < 32; ++w) t += (int)uS.p.wc[w][tid];
        s_off[tid + 1] = t;
    }
    __syncthreads();
    if (tid == 0) {
        s_off[0] = 0;
        int acc = 0;
        for (int c = 1; c <= NCn; ++c) { acc += s_off[c]; s_off[c] = acc; }
    }
    __syncthreads();
    {
        int cross = 0;
        for (int w = 0; w < wid; ++w) cross += (int)uS.p.wc[w][myc];
        s_list[s_off[myc] + cross + within] = (unsigned short)tid;
    }
    __syncthreads();

    // ---- greedy NMS: one WARP per class, inner loop lane-parallel ----
    for (int c = wid; c < NCn; c += 32) {
        const int beg = s_off[c], end = s_off[c + 1];
        for (int m = beg; m < end; ++m) {
            int i = s_list[m];
            unsigned char kf = 0;
            if (s_conf[i] > 0.0f) {
                float ax1 = s_x1[i], ay1 = s_y1[i], ax2 = s_x2[i], ay2 = s_y2[i];
                float areaA = __fmul_rn(__fsub_rn(ax2, ax1), __fsub_rn(ay2, ay1));
                bool sup = false;
                for (int basep = beg; basep < m; basep += 32) {
                    int mm2 = basep + lane;
                    bool hit = false;
                    if (mm2 < m) {
                        int j = s_list[mm2];
                        if (s_keep[j]) {
                            float bx1 = s_x1[j], by1 = s_y1[j], bx2 = s_x2[j], by2 = s_y2[j];
                            float areaB = __fmul_rn(__fsub_rn(bx2, bx1), __fsub_rn(by2, by1));
                            // class shift cancels in lt/rb except via rounding:
                            // reproduce reference exactly by shifting both boxes
                            float sa = __fmul_rn((float)c, 7680.0f);
                            hit = iou_rn(__fadd_rn(ax1, sa), __fadd_rn(ay1, sa),
                                         __fadd_rn(ax2, sa), __fadd_rn(ay2, sa),
                                         __fmul_rn(__fsub_rn(__fadd_rn(ax2, sa), __fadd_rn(ax1, sa)),
                                                   __fsub_rn(__fadd_rn(ay2, sa), __fadd_rn(ay1, sa))),
                                         __fadd_rn(bx1, sa), __fadd_rn(by1, sa),
                                         __fadd_rn(bx2, sa), __fadd_rn(by2, sa),
                                         __fmul_rn(__fsub_rn(__fadd_rn(bx2, sa), __fadd_rn(bx1, sa)),
                                                   __fsub_rn(__fadd_rn(by2, sa), __fadd_rn(by1, sa)))) > 0.45f;
                        }
                    }
                    sup = __any_sync(0xFFFFFFFFu, hit);
                    if (sup) break;
                }
                kf = sup ? 0 : 1;
            }
            if (lane == 0) s_keep[i] = kf;
            __syncwarp();
        }
    }
    __syncthreads();

    // ---- scan keep; cap 300; pv ----
    int inc = warp_incl_scan((int)s_keep[tid], lane);
    if (lane == 31) uS.p.scan_w[wid] = inc;
    __syncthreads();
    if (tid < 32) uS.p.scan_w[tid] = warp_incl_scan(uS.p.scan_w[tid], tid);
    __syncthreads();
    int csum = inc + (wid > 0 ? uS.p.scan_w[wid - 1] : 0);
    int pv = (s_keep[tid] && csum <= MAXDET && s_conf[tid] > 0.5f) ? 1 : 0;
    int n_pred = __syncthreads_count(pv);
    s_keep[tid] = (unsigned char)pv;
    __syncthreads();

    // ---- matching: one warp per GT ----
    {
        const int g = wid;
        float gx1 = s_gtb[g][0], gy1 = s_gtb[g][1], gx2 = s_gtb[g][2], gy2 = s_gtb[g][3];
        float areaG = __fmul_rn(__fsub_rn(gx2, gx1), __fsub_rn(gy2, gy1));
        int gc = s_gtc[g];
        float best = -__int_as_float(0x7f800000);
        int bidx = 0;
        for (int i = lane; i < Kn; i += 32) {
            float vv = -1.0f;
            if (s_keep[i] && (int)s_cls[i] == gc) {
                float ax1 = s_x1[i], ay1 = s_y1[i], ax2 = s_x2[i], ay2 = s_y2[i];
                float areaA = __fmul_rn(__fsub_rn(ax2, ax1), __fsub_rn(ay2, ay1));
                vv = iou_rn(ax1, ay1, ax2, ay2, areaA, gx1, gy1, gx2, gy2, areaG);
            }
            if (vv > best) { best = vv; bidx = i; }
        }
#pragma unroll
        for (int off = 16; off > 0; off >>= 1) {
            float ov = __shfl_down_sync(0xFFFFFFFFu, best, off);
            int   oi = __shfl_down_sync(0xFFFFFFFFu, bidx, off);
            if (ov > best || (ov == best && oi < bidx)) { best = ov; bidx = oi; }
        }
        if (lane == 0) {
            s_biou[g]  = best;
            s_bconf[g] = s_conf[bidx];
            s_hit[g]   = (best > 0.6f) && (s_gtm[g] != 0);
        }
    }
    __syncthreads();

    // ---- final stats ----
    float* bins = (float*)s_hist4;
    if (tid < 96) bins[tid] = 0.0f;
    __syncthreads();
    if (tid < 32) {
        int g = tid;
        float gm = (s_gtm[g] != 0) ? 1.0f : 0.0f;
        int gc = s_gtc[g];
        atomicAdd(&bins[gc], gm);
        atomicAdd(&bins[80 + cat_to_super[gc]], gm);
        float hi = s_hit[g] ? 1.0f : 0.0f;
        float n_gt = gm, n_hit = hi;
        float s_iou = hi * s_biou[g];
        float s_cf  = hi * s_bconf[g];
#pragma unroll
        for (int off = 16; off > 0; off >>= 1) {
            n_gt  += __shfl_down_sync(0xFFFFFFFFu, n_gt,  off);
            n_hit += __shfl_down_sync(0xFFFFFFFFu, n_hit, off);
            s_iou += __shfl_down_sync(0xFFFFFFFFu, s_iou, off);
            s_cf  += __shfl_down_sync(0xFFFFFFFFu, s_cf,  off);
        }
        if (tid == 0) {
            int mfc = 0;
            for (int c = 1; c < NCn; ++c) if (bins[c] > bins[mfc]) mfc = c;
            int mfs = 0;
            for (int s = 1; s < NSUPn; ++s) if (bins[80 + s] > bins[80 + mfs]) mfs = s;
            float fh = n_hit;
            float mean_iou  = __fdiv_rn(s_iou, fmaxf(fh, 1.0f));
            float mean_conf = (n_hit > 0.0f) ? __fdiv_rn(s_cf, fmaxf(fh, 1.0f)) : 1.0f;
            float correct   = __fdiv_rn(fh, fmaxf(n_gt, 1.0f));
            float r0, r1, r2, r3, r4;
            if (n_gt == 0.0f) {
                if (n_pred == 0) { r0 = 1.f; r1 = 1.f; r2 = -1.f; r3 = -1.f; r4 = 1.f; }
                else             { r0 = 0.f; r1 = 1.f; r2 = -2.f; r3 = -2.f; r4 = 0.f; }
            } else {
                r0 = mean_iou; r1 = mean_conf; r2 = (float)mfc; r3 = (float)mfs; r4 = correct;
            }
            out[b * 5 + 0] = r0; out[b * 5 + 1] = r1; out[b * 5 + 2] = r2;
            out[b * 5 + 3] = r3; out[b * 5 + 4] = r4;
        }
    }
}

extern "C" void kernel_launch(void* const* d_in, const int* in_sizes, int n_in,
                              void* d_out, int out_size) {
    const float* preds        = (const float*)d_in[0];
    const float* gt_boxes     = (const float*)d_in[1];
    const int*   gt_cls       = (const int*)d_in[2];
    const int*   gt_mask      = (const int*)d_in[3];
    const int*   cat_to_super = (const int*)d_in[4];
    float* out = (float*)d_out;

    int tot = Bn * (An / 4);
    k1_scores<<<(tot + 255) / 256, 256>>>(preds);
    k2_select<<<Bn, 1024>>>(preds, gt_boxes, gt_cls, gt_mask, cat_to_super, out);
}